// round 13
// baseline (speedup 1.0000x reference)
#include <cuda_runtime.h>
#include <cuda_fp16.h>
#include <cstdint>

// Problem constants (fixed by the dataset)
#define NN 131072          // nodes
#define EE 4194304         // edges
#define F1 128             // input feature dim
#define F2 256             // hidden dim
#define SUB 16             // subgraph group size
#define NG (NN / SUB)      // 8192 output rows
#define CAPLOG 7           // 128 slots per node (max Poisson(32) degree << 128)
#define CAP (1 << CAPLOG)

// ---------------- device scratch (static, no allocation) ----------------
__device__ float  g_dinv[NN];
__device__ int    g_cursor[NN];
__device__ int    g_csrc[(size_t)NN * CAP];  // padded-bucket CSR (64MB)
__device__ int    g_edge64;
__device__ __half g_x16[(size_t)NN * F1];    // x in fp16
__device__ __half g_agg[(size_t)NN * F2];    // agg output (fp16)
__device__ __half g_h16[(size_t)NN * F2];    // h1 in fp16
__device__ __half g_W1t[(size_t)F2 * F1];    // W1^T fp16  [256 x 128]
__device__ __half g_W2t[(size_t)F2 * F2];    // W2^T fp16  [256 x 256]
__device__ float  g_part[(size_t)NG * 4];    // fused-head partials

__device__ __forceinline__ uint32_t smem_u32(const void* p) {
    return (uint32_t)__cvta_generic_to_shared(p);
}

__device__ __forceinline__ void cp16(uint32_t smem_dst, const void* gsrc) {
    asm volatile("cp.async.cg.shared.global [%0], [%1], 16;"
                 :: "r"(smem_dst), "l"(gsrc));
}
__device__ __forceinline__ void cp_commit() {
    asm volatile("cp.async.commit_group;");
}
template <int N>
__device__ __forceinline__ void cp_wait() {
    asm volatile("cp.async.wait_group %0;" :: "n"(N));
}

// mma.sync m16n8k16 f16 (fp32 accumulate); generic PTX, sm_80+.
__device__ __forceinline__ void mma_f16(float* c, const uint32_t* a, const uint32_t* b) {
    asm volatile(
        "mma.sync.aligned.m16n8k16.row.col.f32.f16.f16.f32 "
        "{%0,%1,%2,%3}, {%4,%5,%6,%7}, {%8,%9}, {%0,%1,%2,%3};"
        : "+f"(c[0]), "+f"(c[1]), "+f"(c[2]), "+f"(c[3])
        : "r"(a[0]), "r"(a[1]), "r"(a[2]), "r"(a[3]),
          "r"(b[0]), "r"(b[1]));
}

// vectorized row-slice load/store of V half2 (V = 2 or 4)
template <int V> struct RowV { __half2 v[V]; };
template <int V>
__device__ __forceinline__ RowV<V> ldrow(const __half2* __restrict__ p) {
    RowV<V> r;
    if (V == 2) {
        uint2 u = *(const uint2*)p;
        r.v[0] = *(__half2*)&u.x; r.v[1] = *(__half2*)&u.y;
    } else {
        uint4 u = *(const uint4*)p;
        r.v[0] = *(__half2*)&u.x; r.v[1] = *(__half2*)&u.y;
        r.v[2] = *(__half2*)&u.z; r.v[3] = *(__half2*)&u.w;
    }
    return r;
}
template <int V>
__device__ __forceinline__ void strow(__half2* p, const RowV<V>& r) {
    if (V == 2) {
        uint2 u;
        u.x = *(const uint32_t*)&r.v[0]; u.y = *(const uint32_t*)&r.v[1];
        *(uint2*)p = u;
    } else {
        uint4 u;
        u.x = *(const uint32_t*)&r.v[0]; u.y = *(const uint32_t*)&r.v[1];
        u.z = *(const uint32_t*)&r.v[2]; u.w = *(const uint32_t*)&r.v[3];
        *(uint4*)p = u;
    }
}

// ---------------- init cursors + dtype detect ----------------
// int64 node indices < 2^31 => every odd 32-bit word of the array is 0.
__global__ void k_init(const int* __restrict__ ei32) {
    int i = blockIdx.x * blockDim.x + threadIdx.x;
    if (i < NN) g_cursor[i] = i << CAPLOG;
    if (blockIdx.x == 0) {
        int found = 0;
        for (int j = threadIdx.x; j < 2048; j += 256)
            if (ei32[2 * j + 1] != 0) found = 1;
        found = __syncthreads_or(found);
        if (threadIdx.x == 0) g_edge64 = found ? 0 : 1;
    }
}

// ---------------- merged fill + weight/feature prep ----------------
// Independent work co-scheduled: bucket fill (atomic/latency-bound) overlaps
// with weight transpose + x->fp16 (stream-bound). All depend only on k_init.
#define FP_FILL  (EE / 2)
#define FP_W1    (FP_FILL + F1 * 256)
#define FP_W2    (FP_W1 + F2 * 256)
#define FP_F2H   (FP_W2 + NN * F1 / 4)
__global__ void k_fillprep(const void* __restrict__ ei,
                           const float* __restrict__ x,
                           const float* __restrict__ W1,
                           const float* __restrict__ W2,
                           __half* __restrict__ x16,
                           __half* __restrict__ w1t,
                           __half* __restrict__ w2t) {
    int idx = blockIdx.x * blockDim.x + threadIdx.x;
    if (idx < FP_FILL) {
        int e2 = idx;
        int s0, s1, d0, d1;
        if (g_edge64) {
            ulonglong2 s = ((const ulonglong2*)ei)[e2];
            ulonglong2 d = ((const ulonglong2*)ei)[EE / 2 + e2];
            s0 = (int)s.x; s1 = (int)s.y; d0 = (int)d.x; d1 = (int)d.y;
        } else {
            int2 s = ((const int2*)ei)[e2];
            int2 d = ((const int2*)ei)[EE / 2 + e2];
            s0 = s.x; s1 = s.y; d0 = d.x; d1 = d.y;
        }
        int p0 = atomicAdd(&g_cursor[d0], 1);
        if (p0 < ((d0 + 1) << CAPLOG)) g_csrc[p0] = s0;   // overflow guard
        int p1 = atomicAdd(&g_cursor[d1], 1);
        if (p1 < ((d1 + 1) << CAPLOG)) g_csrc[p1] = s1;
    } else if (idx < FP_W1) {
        int j = idx - FP_FILL;
        int k = j / 256, n = j % 256;
        w1t[(size_t)n * F1 + k] = __float2half_rn(W1[j]);
    } else if (idx < FP_W2) {
        int j = idx - FP_W1;
        int k = j / 256, n = j % 256;
        w2t[(size_t)n * F2 + k] = __float2half_rn(W2[j]);
    } else if (idx < FP_F2H) {
        int j = idx - FP_W2;
        float4 v = ((const float4*)x)[j];
        ((__half2*)x16)[2 * j    ] = __floats2half2_rn(v.x, v.y);
        ((__half2*)x16)[2 * j + 1] = __floats2half2_rn(v.z, v.w);
    }
}

// ---------------- dinv from final cursors ----------------
__global__ void k_dinv() {
    int i = blockIdx.x * blockDim.x + threadIdx.x;
    if (i >= NN) return;
    int deg = g_cursor[i] - (i << CAPLOG) + 1;
    g_dinv[i] = rsqrtf((float)deg);
}

// ---------------- warp-per-node aggregation (round-11 proven inner loop) ----
// out[i,:] = fp16( sum_{e: dst=i} h[src_e,:]*dinv[src]*dinv[i] + h[i,:]*dinv[i]^2 )
// One warp per node; each lane owns V = F/64 half2 columns (8B or 16B slice).
template <int F>
__global__ void __launch_bounds__(256)
k_agg_w(const __half* __restrict__ h, __half* __restrict__ outp) {
    const int T = F / 2;          // half2 per row
    const int V = T / 32;         // half2 per lane: 2 (F1) or 4 (F2)
    int i = (blockIdx.x * 256 + threadIdx.x) >> 5;     // node id
    int lane = threadIdx.x & 31;
    const __half2* __restrict__ base = (const __half2*)h;
    float di = g_dinv[i];

    float acc[2 * V];
    {
        RowV<V> r = ldrow<V>(base + (size_t)i * T + lane * V);
        float dsq = di * di;
#pragma unroll
        for (int v = 0; v < V; v++) {
            float2 f = __half22float2(r.v[v]);
            acc[2 * v    ] = f.x * dsq;
            acc[2 * v + 1] = f.y * dsq;
        }
    }

    int e0 = i << CAPLOG;
    int e1 = g_cursor[i];
    int e = e0;
    for (; e + 4 <= e1; e += 4) {
        int s0 = g_csrc[e    ], s1 = g_csrc[e + 1];
        int s2 = g_csrc[e + 2], s3 = g_csrc[e + 3];
        float w0 = g_dinv[s0] * di, w1 = g_dinv[s1] * di;
        float w2 = g_dinv[s2] * di, w3 = g_dinv[s3] * di;
        RowV<V> r0 = ldrow<V>(base + (size_t)s0 * T + lane * V);
        RowV<V> r1 = ldrow<V>(base + (size_t)s1 * T + lane * V);
        RowV<V> r2 = ldrow<V>(base + (size_t)s2 * T + lane * V);
        RowV<V> r3 = ldrow<V>(base + (size_t)s3 * T + lane * V);
#pragma unroll
        for (int v = 0; v < V; v++) {
            float2 f0 = __half22float2(r0.v[v]);
            float2 f1 = __half22float2(r1.v[v]);
            float2 f2 = __half22float2(r2.v[v]);
            float2 f3 = __half22float2(r3.v[v]);
            acc[2 * v    ] = fmaf(f0.x, w0, acc[2 * v    ]);
            acc[2 * v + 1] = fmaf(f0.y, w0, acc[2 * v + 1]);
            acc[2 * v    ] = fmaf(f1.x, w1, acc[2 * v    ]);
            acc[2 * v + 1] = fmaf(f1.y, w1, acc[2 * v + 1]);
            acc[2 * v    ] = fmaf(f2.x, w2, acc[2 * v    ]);
            acc[2 * v + 1] = fmaf(f2.y, w2, acc[2 * v + 1]);
            acc[2 * v    ] = fmaf(f3.x, w3, acc[2 * v    ]);
            acc[2 * v + 1] = fmaf(f3.y, w3, acc[2 * v + 1]);
        }
    }
    for (; e < e1; e++) {
        int s = g_csrc[e];
        float w = g_dinv[s] * di;
        RowV<V> r = ldrow<V>(base + (size_t)s * T + lane * V);
#pragma unroll
        for (int v = 0; v < V; v++) {
            float2 f = __half22float2(r.v[v]);
            acc[2 * v    ] = fmaf(f.x, w, acc[2 * v    ]);
            acc[2 * v + 1] = fmaf(f.y, w, acc[2 * v + 1]);
        }
    }

    RowV<V> o;
#pragma unroll
    for (int v = 0; v < V; v++)
        o.v[v] = __floats2half2_rn(acc[2 * v], acc[2 * v + 1]);
    strow<V>((__half2*)outp + (size_t)i * T + lane * V, o);
}

// ---------------- fp16 mma.sync GEMM, cp.async double-buffered ----------------
// out[M,256] = relu(A[M,K] @ Wt^T + bias) -> fp16.
template <int K>
__global__ void __launch_bounds__(256)
k_gemm_h(const __half* __restrict__ A, const __half* __restrict__ Wt,
         const float* __restrict__ bias, __half* __restrict__ out) {
    const int BK = 32, LD = BK + 8;
    __shared__ __half As[2][128][LD];
    __shared__ __half Bs[2][128][LD];

    int tid = threadIdx.x;
    int lane = tid & 31;
    int warp = tid >> 5;
    int warp_m = warp & 3;
    int warp_n = warp >> 2;
    int gid = lane >> 2;
    int tig = lane & 3;
    int m0 = blockIdx.y * 128;
    int n0 = blockIdx.x * 128;

    float c[2][8][4];
#pragma unroll
    for (int mm = 0; mm < 2; mm++)
#pragma unroll
        for (int nn = 0; nn < 8; nn++)
#pragma unroll
            for (int q = 0; q < 4; q++) c[mm][nn][q] = 0.0f;

    int srow0 = tid >> 2, sc0 = (tid & 3) * 8;
    int srow1 = (tid + 256) >> 2, sc1 = sc0;
    const int NCH = K / BK;

    cp16(smem_u32(&As[0][srow0][sc0]), &A[(size_t)(m0 + srow0) * K + sc0]);
    cp16(smem_u32(&Bs[0][srow0][sc0]), &Wt[(size_t)(n0 + srow0) * K + sc0]);
    cp16(smem_u32(&As[0][srow1][sc1]), &A[(size_t)(m0 + srow1) * K + sc1]);
    cp16(smem_u32(&Bs[0][srow1][sc1]), &Wt[(size_t)(n0 + srow1) * K + sc1]);
    cp_commit();

#pragma unroll
    for (int ch = 0; ch < NCH; ch++) {
        int buf = ch & 1;
        if (ch + 1 < NCH) {
            int nb = buf ^ 1, kofs = (ch + 1) * BK;
            cp16(smem_u32(&As[nb][srow0][sc0]), &A[(size_t)(m0 + srow0) * K + kofs + sc0]);
            cp16(smem_u32(&Bs[nb][srow0][sc0]), &Wt[(size_t)(n0 + srow0) * K + kofs + sc0]);
            cp16(smem_u32(&As[nb][srow1][sc1]), &A[(size_t)(m0 + srow1) * K + kofs + sc1]);
            cp16(smem_u32(&Bs[nb][srow1][sc1]), &Wt[(size_t)(n0 + srow1) * K + kofs + sc1]);
        }
        cp_commit();
        cp_wait<1>();
        __syncthreads();

#pragma unroll
        for (int kk = 0; kk < 2; kk++) {
            int kb = kk * 16;
            uint32_t a[2][4], b[8][2];
#pragma unroll
            for (int mm = 0; mm < 2; mm++) {
                int r = warp_m * 32 + mm * 16;
                a[mm][0] = *(const uint32_t*)&As[buf][r + gid    ][kb + 2 * tig    ];
                a[mm][1] = *(const uint32_t*)&As[buf][r + gid + 8][kb + 2 * tig    ];
                a[mm][2] = *(const uint32_t*)&As[buf][r + gid    ][kb + 2 * tig + 8];
                a[mm][3] = *(const uint32_t*)&As[buf][r + gid + 8][kb + 2 * tig + 8];
            }
#pragma unroll
            for (int nn = 0; nn < 8; nn++) {
                int r = warp_n * 64 + nn * 8;
                b[nn][0] = *(const uint32_t*)&Bs[buf][r + gid][kb + 2 * tig    ];
                b[nn][1] = *(const uint32_t*)&Bs[buf][r + gid][kb + 2 * tig + 8];
            }
#pragma unroll
            for (int mm = 0; mm < 2; mm++)
#pragma unroll
                for (int nn = 0; nn < 8; nn++)
                    mma_f16(c[mm][nn], a[mm], b[nn]);
        }
        __syncthreads();
    }

#pragma unroll
    for (int mm = 0; mm < 2; mm++) {
        int rbase = m0 + warp_m * 32 + mm * 16;
#pragma unroll
        for (int nn = 0; nn < 8; nn++) {
            int col = n0 + warp_n * 64 + nn * 8 + tig * 2;
            float bi0 = bias[col], bi1 = bias[col + 1];
            float v00 = fmaxf(c[mm][nn][0] + bi0, 0.0f);
            float v01 = fmaxf(c[mm][nn][1] + bi1, 0.0f);
            float v10 = fmaxf(c[mm][nn][2] + bi0, 0.0f);
            float v11 = fmaxf(c[mm][nn][3] + bi1, 0.0f);
            *(__half2*)&out[(size_t)(rbase + gid    ) * F2 + col] = __floats2half2_rn(v00, v01);
            *(__half2*)&out[(size_t)(rbase + gid + 8) * F2 + col] = __floats2half2_rn(v10, v11);
        }
    }
}

// ---------------- layer-2 GEMM with fused output head ----------------
template <int K>
__global__ void __launch_bounds__(256)
k_gemm_fin(const __half* __restrict__ A, const __half* __restrict__ Wt,
           const float* __restrict__ bias, const float* __restrict__ Wout) {
    const int BK = 32, LD = BK + 8;
    __shared__ __half As[2][128][LD];
    __shared__ __half Bs[2][128][LD];

    int tid = threadIdx.x;
    int lane = tid & 31;
    int warp = tid >> 5;
    int warp_m = warp & 3;
    int warp_n = warp >> 2;
    int gid = lane >> 2;
    int tig = lane & 3;
    int m0 = blockIdx.y * 128;
    int n0 = blockIdx.x * 128;

    float c[2][8][4];
#pragma unroll
    for (int mm = 0; mm < 2; mm++)
#pragma unroll
        for (int nn = 0; nn < 8; nn++)
#pragma unroll
            for (int q = 0; q < 4; q++) c[mm][nn][q] = 0.0f;

    int srow0 = tid >> 2, sc0 = (tid & 3) * 8;
    int srow1 = (tid + 256) >> 2, sc1 = sc0;
    const int NCH = K / BK;

    cp16(smem_u32(&As[0][srow0][sc0]), &A[(size_t)(m0 + srow0) * K + sc0]);
    cp16(smem_u32(&Bs[0][srow0][sc0]), &Wt[(size_t)(n0 + srow0) * K + sc0]);
    cp16(smem_u32(&As[0][srow1][sc1]), &A[(size_t)(m0 + srow1) * K + sc1]);
    cp16(smem_u32(&Bs[0][srow1][sc1]), &Wt[(size_t)(n0 + srow1) * K + sc1]);
    cp_commit();

#pragma unroll
    for (int ch = 0; ch < NCH; ch++) {
        int buf = ch & 1;
        if (ch + 1 < NCH) {
            int nb = buf ^ 1, kofs = (ch + 1) * BK;
            cp16(smem_u32(&As[nb][srow0][sc0]), &A[(size_t)(m0 + srow0) * K + kofs + sc0]);
            cp16(smem_u32(&Bs[nb][srow0][sc0]), &Wt[(size_t)(n0 + srow0) * K + kofs + sc0]);
            cp16(smem_u32(&As[nb][srow1][sc1]), &A[(size_t)(m0 + srow1) * K + kofs + sc1]);
            cp16(smem_u32(&Bs[nb][srow1][sc1]), &Wt[(size_t)(n0 + srow1) * K + kofs + sc1]);
        }
        cp_commit();
        cp_wait<1>();
        __syncthreads();

#pragma unroll
        for (int kk = 0; kk < 2; kk++) {
            int kb = kk * 16;
            uint32_t a[2][4], b[8][2];
#pragma unroll
            for (int mm = 0; mm < 2; mm++) {
                int r = warp_m * 32 + mm * 16;
                a[mm][0] = *(const uint32_t*)&As[buf][r + gid    ][kb + 2 * tig    ];
                a[mm][1] = *(const uint32_t*)&As[buf][r + gid + 8][kb + 2 * tig    ];
                a[mm][2] = *(const uint32_t*)&As[buf][r + gid    ][kb + 2 * tig + 8];
                a[mm][3] = *(const uint32_t*)&As[buf][r + gid + 8][kb + 2 * tig + 8];
            }
#pragma unroll
            for (int nn = 0; nn < 8; nn++) {
                int r = warp_n * 64 + nn * 8;
                b[nn][0] = *(const uint32_t*)&Bs[buf][r + gid][kb + 2 * tig    ];
                b[nn][1] = *(const uint32_t*)&Bs[buf][r + gid][kb + 2 * tig + 8];
            }
#pragma unroll
            for (int mm = 0; mm < 2; mm++)
#pragma unroll
                for (int nn = 0; nn < 8; nn++)
                    mma_f16(c[mm][nn], a[mm], b[nn]);
        }
        __syncthreads();
    }

    // fused epilogue: relu(c + bias) dot Wout[(row&15)*256 + col]
    float vsum[2] = {0.0f, 0.0f};
#pragma unroll
    for (int mm = 0; mm < 2; mm++) {
#pragma unroll
        for (int nn = 0; nn < 8; nn++) {
            int col = n0 + warp_n * 64 + nn * 8 + tig * 2;
            float bi0 = bias[col], bi1 = bias[col + 1];
            float v00 = fmaxf(c[mm][nn][0] + bi0, 0.0f);
            float v01 = fmaxf(c[mm][nn][1] + bi1, 0.0f);
            float v10 = fmaxf(c[mm][nn][2] + bi0, 0.0f);
            float v11 = fmaxf(c[mm][nn][3] + bi1, 0.0f);
            float w00 = Wout[gid * 256 + col];
            float w01 = Wout[gid * 256 + col + 1];
            float w10 = Wout[(gid + 8) * 256 + col];
            float w11 = Wout[(gid + 8) * 256 + col + 1];
            vsum[mm] += v00 * w00 + v01 * w01 + v10 * w10 + v11 * w11;
        }
    }
#pragma unroll
    for (int off = 16; off > 0; off >>= 1) {
        vsum[0] += __shfl_down_sync(0xFFFFFFFF, vsum[0], off);
        vsum[1] += __shfl_down_sync(0xFFFFFFFF, vsum[1], off);
    }
    if (lane == 0) {
        int quarter = blockIdx.x * 2 + warp_n;
#pragma unroll
        for (int mm = 0; mm < 2; mm++) {
            int group = (m0 >> 4) + warp_m * 2 + mm;
            g_part[(size_t)group * 4 + quarter] = vsum[mm];
        }
    }
}

// ---------------- finisher: sum 4 partials + bias ----------------
__global__ void k_fin(const float* __restrict__ bout, float* __restrict__ out) {
    int g = blockIdx.x * blockDim.x + threadIdx.x;
    if (g >= NG) return;
    float4 p = *(const float4*)&g_part[(size_t)g * 4];
    out[g] = p.x + p.y + p.z + p.w + bout[0];
}

// ---------------- launch ----------------
extern "C" void kernel_launch(void* const* d_in, const int* in_sizes, int n_in,
                              void* d_out, int out_size) {
    const float* x    = (const float*)d_in[0];
    const void*  ei   = d_in[1];
    const float* W1   = (const float*)d_in[2];
    const float* b1   = (const float*)d_in[3];
    const float* W2   = (const float*)d_in[4];
    const float* b2   = (const float*)d_in[5];
    const float* Wout = (const float*)d_in[6];
    const float* bout = (const float*)d_in[7];
    float* out = (float*)d_out;

    __half *x16, *agg, *h16, *w1t, *w2t;
    cudaGetSymbolAddress((void**)&x16, g_x16);
    cudaGetSymbolAddress((void**)&agg, g_agg);
    cudaGetSymbolAddress((void**)&h16, g_h16);
    cudaGetSymbolAddress((void**)&w1t, g_W1t);
    cudaGetSymbolAddress((void**)&w2t, g_W2t);

    // graph build + prep (fill/wt/f2h co-scheduled in one kernel)
    k_init<<<NN / 256, 256>>>((const int*)ei);                          // launch 1
    k_fillprep<<<(FP_F2H + 255) / 256, 256>>>(ei, x, W1, W2, x16, w1t, w2t); // launch 2
    k_dinv<<<NN / 256, 256>>>();                                        // launch 3

    // layer 1: warp-per-node aggregate then fp16 GEMM -> fp16 h1
    k_agg_w<F1><<<NN * 32 / 256, 256>>>(x16, agg);                      // launch 4
    {
        dim3 grid(F2 / 128, NN / 128);
        k_gemm_h<F1><<<grid, 256>>>(agg, w1t, b1, h16);                 // launch 5
    }
    // layer 2: warp-per-node aggregate then fp16 GEMM fused with output head
    k_agg_w<F2><<<NN * 32 / 256, 256>>>(h16, agg);                      // launch 6
    {
        dim3 grid(F2 / 128, NN / 128);
        k_gemm_fin<F2><<<grid, 256>>>(agg, w2t, b2, Wout);              // launch 7
    }
    // finisher
    k_fin<<<NG / 256, 256>>>(bout, out);                                // launch 8
}

// round 14
// speedup vs baseline: 1.1683x; 1.1683x over previous
#include <cuda_runtime.h>
#include <cuda_fp16.h>
#include <cstdint>

// Problem constants (fixed by the dataset)
#define NN 131072          // nodes
#define EE 4194304         // edges
#define F1 128             // input feature dim
#define F2 256             // hidden dim
#define SUB 16             // subgraph group size
#define NG (NN / SUB)      // 8192 output rows
#define CAPLOG 7           // 128 slots per node (max Poisson(32) degree << 128)
#define CAP (1 << CAPLOG)

// ---------------- device scratch (static, no allocation) ----------------
__device__ float  g_dinv[NN];
__device__ int    g_cursor[NN];
__device__ int    g_csrc[(size_t)NN * CAP];  // padded-bucket CSR (64MB)
__device__ int    g_edge64;
__device__ __half g_x16[(size_t)NN * F1];    // y0 = x*dinv in fp16
__device__ __half g_agg[(size_t)NN * F2];    // agg output (fp16)
__device__ __half g_h16[(size_t)NN * F2];    // y1 = h1*dinv in fp16
__device__ __half g_W1t[(size_t)F2 * F1];    // W1^T fp16  [256 x 128]
__device__ __half g_W2t[(size_t)F2 * F2];    // W2^T fp16  [256 x 256]
__device__ float  g_part[(size_t)NG * 4];    // fused-head partials

__device__ __forceinline__ uint32_t smem_u32(const void* p) {
    return (uint32_t)__cvta_generic_to_shared(p);
}

__device__ __forceinline__ void cp16(uint32_t smem_dst, const void* gsrc) {
    asm volatile("cp.async.cg.shared.global [%0], [%1], 16;"
                 :: "r"(smem_dst), "l"(gsrc));
}
__device__ __forceinline__ void cp_commit() {
    asm volatile("cp.async.commit_group;");
}
template <int N>
__device__ __forceinline__ void cp_wait() {
    asm volatile("cp.async.wait_group %0;" :: "n"(N));
}

// mma.sync m16n8k16 f16 (fp32 accumulate); generic PTX, sm_80+.
__device__ __forceinline__ void mma_f16(float* c, const uint32_t* a, const uint32_t* b) {
    asm volatile(
        "mma.sync.aligned.m16n8k16.row.col.f32.f16.f16.f32 "
        "{%0,%1,%2,%3}, {%4,%5,%6,%7}, {%8,%9}, {%0,%1,%2,%3};"
        : "+f"(c[0]), "+f"(c[1]), "+f"(c[2]), "+f"(c[3])
        : "r"(a[0]), "r"(a[1]), "r"(a[2]), "r"(a[3]),
          "r"(b[0]), "r"(b[1]));
}

// vectorized row-slice load/store of V half2 (V = 2 or 4)
template <int V> struct RowV { __half2 v[V]; };
template <int V>
__device__ __forceinline__ RowV<V> ldrow(const __half2* __restrict__ p) {
    RowV<V> r;
    if (V == 2) {
        uint2 u = *(const uint2*)p;
        r.v[0] = *(__half2*)&u.x; r.v[1] = *(__half2*)&u.y;
    } else {
        uint4 u = *(const uint4*)p;
        r.v[0] = *(__half2*)&u.x; r.v[1] = *(__half2*)&u.y;
        r.v[2] = *(__half2*)&u.z; r.v[3] = *(__half2*)&u.w;
    }
    return r;
}
template <int V>
__device__ __forceinline__ void strow(__half2* p, const RowV<V>& r) {
    if (V == 2) {
        uint2 u;
        u.x = *(const uint32_t*)&r.v[0]; u.y = *(const uint32_t*)&r.v[1];
        *(uint2*)p = u;
    } else {
        uint4 u;
        u.x = *(const uint32_t*)&r.v[0]; u.y = *(const uint32_t*)&r.v[1];
        u.z = *(const uint32_t*)&r.v[2]; u.w = *(const uint32_t*)&r.v[3];
        *(uint4*)p = u;
    }
}

// ---------------- init cursors + dtype detect ----------------
// int64 node indices < 2^31 => every odd 32-bit word of the array is 0.
__global__ void k_init(const int* __restrict__ ei32) {
    int i = blockIdx.x * blockDim.x + threadIdx.x;
    if (i < NN) g_cursor[i] = i << CAPLOG;
    if (blockIdx.x == 0) {
        int found = 0;
        for (int j = threadIdx.x; j < 2048; j += 256)
            if (ei32[2 * j + 1] != 0) found = 1;
        found = __syncthreads_or(found);
        if (threadIdx.x == 0) g_edge64 = found ? 0 : 1;
    }
}

// ---------------- merged fill + weight transpose ----------------
#define FP_FILL  (EE / 2)
#define FP_W1    (FP_FILL + F1 * 256)
#define FP_W2    (FP_W1 + F2 * 256)
__global__ void k_fillprep(const void* __restrict__ ei,
                           const float* __restrict__ W1,
                           const float* __restrict__ W2,
                           __half* __restrict__ w1t,
                           __half* __restrict__ w2t) {
    int idx = blockIdx.x * blockDim.x + threadIdx.x;
    if (idx < FP_FILL) {
        int e2 = idx;
        int s0, s1, d0, d1;
        if (g_edge64) {
            ulonglong2 s = ((const ulonglong2*)ei)[e2];
            ulonglong2 d = ((const ulonglong2*)ei)[EE / 2 + e2];
            s0 = (int)s.x; s1 = (int)s.y; d0 = (int)d.x; d1 = (int)d.y;
        } else {
            int2 s = ((const int2*)ei)[e2];
            int2 d = ((const int2*)ei)[EE / 2 + e2];
            s0 = s.x; s1 = s.y; d0 = d.x; d1 = d.y;
        }
        int p0 = atomicAdd(&g_cursor[d0], 1);
        if (p0 < ((d0 + 1) << CAPLOG)) g_csrc[p0] = s0;   // overflow guard
        int p1 = atomicAdd(&g_cursor[d1], 1);
        if (p1 < ((d1 + 1) << CAPLOG)) g_csrc[p1] = s1;
    } else if (idx < FP_W1) {
        int j = idx - FP_FILL;
        int k = j / 256, n = j % 256;
        w1t[(size_t)n * F1 + k] = __float2half_rn(W1[j]);
    } else if (idx < FP_W2) {
        int j = idx - FP_W1;
        int k = j / 256, n = j % 256;
        w2t[(size_t)n * F2 + k] = __float2half_rn(W2[j]);
    }
}

// ---------------- prep2: dinv + prescaled x->fp16 ----------------
// Range A stores dinv; range B computes y0 = x*dinv(row) with dinv derived
// locally from cursors (read-only — no race with range A).
#define P2_DINV NN
#define P2_F2H  (P2_DINV + NN * F1 / 4)
__global__ void k_prep2(const float* __restrict__ x, __half* __restrict__ x16) {
    int idx = blockIdx.x * blockDim.x + threadIdx.x;
    if (idx < P2_DINV) {
        int deg = g_cursor[idx] - (idx << CAPLOG) + 1;
        g_dinv[idx] = rsqrtf((float)deg);
    } else if (idx < P2_F2H) {
        int j = idx - P2_DINV;                 // over NN*F1/4
        int row = j >> 5;                      // j / (F1/4)
        int deg = g_cursor[row] - (row << CAPLOG) + 1;
        float di = rsqrtf((float)deg);
        float4 v = ((const float4*)x)[j];
        ((__half2*)x16)[2 * j    ] = __floats2half2_rn(v.x * di, v.y * di);
        ((__half2*)x16)[2 * j + 1] = __floats2half2_rn(v.z * di, v.w * di);
    }
}

// ---------------- warp-per-node aggregation (prescaled inputs) ----------
// Input rows y[s] = dinv[s]*h[s]; out[i,:] = fp16( dinv[i] * (y[i] + sum y[src]) )
// Round-11 loop skeleton with the per-edge dinv gather and FMUL removed.
template <int F>
__global__ void __launch_bounds__(256)
k_agg_w(const __half* __restrict__ h, __half* __restrict__ outp) {
    const int T = F / 2;          // half2 per row
    const int V = T / 32;         // half2 per lane: 2 (F1) or 4 (F2)
    int i = (blockIdx.x * 256 + threadIdx.x) >> 5;     // node id
    int lane = threadIdx.x & 31;
    const __half2* __restrict__ base = (const __half2*)h;
    float di = g_dinv[i];

    float acc[2 * V];
    {
        RowV<V> r = ldrow<V>(base + (size_t)i * T + lane * V);
#pragma unroll
        for (int v = 0; v < V; v++) {
            float2 f = __half22float2(r.v[v]);
            acc[2 * v    ] = f.x;
            acc[2 * v + 1] = f.y;
        }
    }

    int e0 = i << CAPLOG;
    int e1 = g_cursor[i];
    int e = e0;
    for (; e + 4 <= e1; e += 4) {
        int s0 = g_csrc[e    ], s1 = g_csrc[e + 1];
        int s2 = g_csrc[e + 2], s3 = g_csrc[e + 3];
        RowV<V> r0 = ldrow<V>(base + (size_t)s0 * T + lane * V);
        RowV<V> r1 = ldrow<V>(base + (size_t)s1 * T + lane * V);
        RowV<V> r2 = ldrow<V>(base + (size_t)s2 * T + lane * V);
        RowV<V> r3 = ldrow<V>(base + (size_t)s3 * T + lane * V);
#pragma unroll
        for (int v = 0; v < V; v++) {
            float2 f0 = __half22float2(r0.v[v]);
            float2 f1 = __half22float2(r1.v[v]);
            float2 f2 = __half22float2(r2.v[v]);
            float2 f3 = __half22float2(r3.v[v]);
            acc[2 * v    ] += f0.x; acc[2 * v + 1] += f0.y;
            acc[2 * v    ] += f1.x; acc[2 * v + 1] += f1.y;
            acc[2 * v    ] += f2.x; acc[2 * v + 1] += f2.y;
            acc[2 * v    ] += f3.x; acc[2 * v + 1] += f3.y;
        }
    }
    for (; e < e1; e++) {
        int s = g_csrc[e];
        RowV<V> r = ldrow<V>(base + (size_t)s * T + lane * V);
#pragma unroll
        for (int v = 0; v < V; v++) {
            float2 f = __half22float2(r.v[v]);
            acc[2 * v    ] += f.x;
            acc[2 * v + 1] += f.y;
        }
    }

    RowV<V> o;
#pragma unroll
    for (int v = 0; v < V; v++)
        o.v[v] = __floats2half2_rn(acc[2 * v] * di, acc[2 * v + 1] * di);
    strow<V>((__half2*)outp + (size_t)i * T + lane * V, o);
}

// ---------------- fp16 mma.sync GEMM, cp.async double-buffered ----------------
// out[M,256] = fp16( relu(A[M,K] @ Wt^T + bias) * dinv[row] )  (prescale for next agg)
template <int K>
__global__ void __launch_bounds__(256)
k_gemm_h(const __half* __restrict__ A, const __half* __restrict__ Wt,
         const float* __restrict__ bias, __half* __restrict__ out) {
    const int BK = 32, LD = BK + 8;
    __shared__ __half As[2][128][LD];
    __shared__ __half Bs[2][128][LD];

    int tid = threadIdx.x;
    int lane = tid & 31;
    int warp = tid >> 5;
    int warp_m = warp & 3;
    int warp_n = warp >> 2;
    int gid = lane >> 2;
    int tig = lane & 3;
    int m0 = blockIdx.y * 128;
    int n0 = blockIdx.x * 128;

    float c[2][8][4];
#pragma unroll
    for (int mm = 0; mm < 2; mm++)
#pragma unroll
        for (int nn = 0; nn < 8; nn++)
#pragma unroll
            for (int q = 0; q < 4; q++) c[mm][nn][q] = 0.0f;

    int srow0 = tid >> 2, sc0 = (tid & 3) * 8;
    int srow1 = (tid + 256) >> 2, sc1 = sc0;
    const int NCH = K / BK;

    cp16(smem_u32(&As[0][srow0][sc0]), &A[(size_t)(m0 + srow0) * K + sc0]);
    cp16(smem_u32(&Bs[0][srow0][sc0]), &Wt[(size_t)(n0 + srow0) * K + sc0]);
    cp16(smem_u32(&As[0][srow1][sc1]), &A[(size_t)(m0 + srow1) * K + sc1]);
    cp16(smem_u32(&Bs[0][srow1][sc1]), &Wt[(size_t)(n0 + srow1) * K + sc1]);
    cp_commit();

#pragma unroll
    for (int ch = 0; ch < NCH; ch++) {
        int buf = ch & 1;
        if (ch + 1 < NCH) {
            int nb = buf ^ 1, kofs = (ch + 1) * BK;
            cp16(smem_u32(&As[nb][srow0][sc0]), &A[(size_t)(m0 + srow0) * K + kofs + sc0]);
            cp16(smem_u32(&Bs[nb][srow0][sc0]), &Wt[(size_t)(n0 + srow0) * K + kofs + sc0]);
            cp16(smem_u32(&As[nb][srow1][sc1]), &A[(size_t)(m0 + srow1) * K + kofs + sc1]);
            cp16(smem_u32(&Bs[nb][srow1][sc1]), &Wt[(size_t)(n0 + srow1) * K + kofs + sc1]);
        }
        cp_commit();
        cp_wait<1>();
        __syncthreads();

#pragma unroll
        for (int kk = 0; kk < 2; kk++) {
            int kb = kk * 16;
            uint32_t a[2][4], b[8][2];
#pragma unroll
            for (int mm = 0; mm < 2; mm++) {
                int r = warp_m * 32 + mm * 16;
                a[mm][0] = *(const uint32_t*)&As[buf][r + gid    ][kb + 2 * tig    ];
                a[mm][1] = *(const uint32_t*)&As[buf][r + gid + 8][kb + 2 * tig    ];
                a[mm][2] = *(const uint32_t*)&As[buf][r + gid    ][kb + 2 * tig + 8];
                a[mm][3] = *(const uint32_t*)&As[buf][r + gid + 8][kb + 2 * tig + 8];
            }
#pragma unroll
            for (int nn = 0; nn < 8; nn++) {
                int r = warp_n * 64 + nn * 8;
                b[nn][0] = *(const uint32_t*)&Bs[buf][r + gid][kb + 2 * tig    ];
                b[nn][1] = *(const uint32_t*)&Bs[buf][r + gid][kb + 2 * tig + 8];
            }
#pragma unroll
            for (int mm = 0; mm < 2; mm++)
#pragma unroll
                for (int nn = 0; nn < 8; nn++)
                    mma_f16(c[mm][nn], a[mm], b[nn]);
        }
        __syncthreads();
    }

#pragma unroll
    for (int mm = 0; mm < 2; mm++) {
        int rbase = m0 + warp_m * 32 + mm * 16;
        float dA = g_dinv[rbase + gid];
        float dB = g_dinv[rbase + gid + 8];
#pragma unroll
        for (int nn = 0; nn < 8; nn++) {
            int col = n0 + warp_n * 64 + nn * 8 + tig * 2;
            float bi0 = bias[col], bi1 = bias[col + 1];
            float v00 = fmaxf(c[mm][nn][0] + bi0, 0.0f) * dA;
            float v01 = fmaxf(c[mm][nn][1] + bi1, 0.0f) * dA;
            float v10 = fmaxf(c[mm][nn][2] + bi0, 0.0f) * dB;
            float v11 = fmaxf(c[mm][nn][3] + bi1, 0.0f) * dB;
            *(__half2*)&out[(size_t)(rbase + gid    ) * F2 + col] = __floats2half2_rn(v00, v01);
            *(__half2*)&out[(size_t)(rbase + gid + 8) * F2 + col] = __floats2half2_rn(v10, v11);
        }
    }
}

// ---------------- layer-2 GEMM with fused output head (no prescale) --------
template <int K>
__global__ void __launch_bounds__(256)
k_gemm_fin(const __half* __restrict__ A, const __half* __restrict__ Wt,
           const float* __restrict__ bias, const float* __restrict__ Wout) {
    const int BK = 32, LD = BK + 8;
    __shared__ __half As[2][128][LD];
    __shared__ __half Bs[2][128][LD];

    int tid = threadIdx.x;
    int lane = tid & 31;
    int warp = tid >> 5;
    int warp_m = warp & 3;
    int warp_n = warp >> 2;
    int gid = lane >> 2;
    int tig = lane & 3;
    int m0 = blockIdx.y * 128;
    int n0 = blockIdx.x * 128;

    float c[2][8][4];
#pragma unroll
    for (int mm = 0; mm < 2; mm++)
#pragma unroll
        for (int nn = 0; nn < 8; nn++)
#pragma unroll
            for (int q = 0; q < 4; q++) c[mm][nn][q] = 0.0f;

    int srow0 = tid >> 2, sc0 = (tid & 3) * 8;
    int srow1 = (tid + 256) >> 2, sc1 = sc0;
    const int NCH = K / BK;

    cp16(smem_u32(&As[0][srow0][sc0]), &A[(size_t)(m0 + srow0) * K + sc0]);
    cp16(smem_u32(&Bs[0][srow0][sc0]), &Wt[(size_t)(n0 + srow0) * K + sc0]);
    cp16(smem_u32(&As[0][srow1][sc1]), &A[(size_t)(m0 + srow1) * K + sc1]);
    cp16(smem_u32(&Bs[0][srow1][sc1]), &Wt[(size_t)(n0 + srow1) * K + sc1]);
    cp_commit();

#pragma unroll
    for (int ch = 0; ch < NCH; ch++) {
        int buf = ch & 1;
        if (ch + 1 < NCH) {
            int nb = buf ^ 1, kofs = (ch + 1) * BK;
            cp16(smem_u32(&As[nb][srow0][sc0]), &A[(size_t)(m0 + srow0) * K + kofs + sc0]);
            cp16(smem_u32(&Bs[nb][srow0][sc0]), &Wt[(size_t)(n0 + srow0) * K + kofs + sc0]);
            cp16(smem_u32(&As[nb][srow1][sc1]), &A[(size_t)(m0 + srow1) * K + kofs + sc1]);
            cp16(smem_u32(&Bs[nb][srow1][sc1]), &Wt[(size_t)(n0 + srow1) * K + kofs + sc1]);
        }
        cp_commit();
        cp_wait<1>();
        __syncthreads();

#pragma unroll
        for (int kk = 0; kk < 2; kk++) {
            int kb = kk * 16;
            uint32_t a[2][4], b[8][2];
#pragma unroll
            for (int mm = 0; mm < 2; mm++) {
                int r = warp_m * 32 + mm * 16;
                a[mm][0] = *(const uint32_t*)&As[buf][r + gid    ][kb + 2 * tig    ];
                a[mm][1] = *(const uint32_t*)&As[buf][r + gid + 8][kb + 2 * tig    ];
                a[mm][2] = *(const uint32_t*)&As[buf][r + gid    ][kb + 2 * tig + 8];
                a[mm][3] = *(const uint32_t*)&As[buf][r + gid + 8][kb + 2 * tig + 8];
            }
#pragma unroll
            for (int nn = 0; nn < 8; nn++) {
                int r = warp_n * 64 + nn * 8;
                b[nn][0] = *(const uint32_t*)&Bs[buf][r + gid][kb + 2 * tig    ];
                b[nn][1] = *(const uint32_t*)&Bs[buf][r + gid][kb + 2 * tig + 8];
            }
#pragma unroll
            for (int mm = 0; mm < 2; mm++)
#pragma unroll
                for (int nn = 0; nn < 8; nn++)
                    mma_f16(c[mm][nn], a[mm], b[nn]);
        }
        __syncthreads();
    }

    // fused epilogue: relu(c + bias) dot Wout[(row&15)*256 + col]
    float vsum[2] = {0.0f, 0.0f};
#pragma unroll
    for (int mm = 0; mm < 2; mm++) {
#pragma unroll
        for (int nn = 0; nn < 8; nn++) {
            int col = n0 + warp_n * 64 + nn * 8 + tig * 2;
            float bi0 = bias[col], bi1 = bias[col + 1];
            float v00 = fmaxf(c[mm][nn][0] + bi0, 0.0f);
            float v01 = fmaxf(c[mm][nn][1] + bi1, 0.0f);
            float v10 = fmaxf(c[mm][nn][2] + bi0, 0.0f);
            float v11 = fmaxf(c[mm][nn][3] + bi1, 0.0f);
            float w00 = Wout[gid * 256 + col];
            float w01 = Wout[gid * 256 + col + 1];
            float w10 = Wout[(gid + 8) * 256 + col];
            float w11 = Wout[(gid + 8) * 256 + col + 1];
            vsum[mm] += v00 * w00 + v01 * w01 + v10 * w10 + v11 * w11;
        }
    }
#pragma unroll
    for (int off = 16; off > 0; off >>= 1) {
        vsum[0] += __shfl_down_sync(0xFFFFFFFF, vsum[0], off);
        vsum[1] += __shfl_down_sync(0xFFFFFFFF, vsum[1], off);
    }
    if (lane == 0) {
        int quarter = blockIdx.x * 2 + warp_n;
#pragma unroll
        for (int mm = 0; mm < 2; mm++) {
            int group = (m0 >> 4) + warp_m * 2 + mm;
            g_part[(size_t)group * 4 + quarter] = vsum[mm];
        }
    }
}

// ---------------- finisher: sum 4 partials + bias ----------------
__global__ void k_fin(const float* __restrict__ bout, float* __restrict__ out) {
    int g = blockIdx.x * blockDim.x + threadIdx.x;
    if (g >= NG) return;
    float4 p = *(const float4*)&g_part[(size_t)g * 4];
    out[g] = p.x + p.y + p.z + p.w + bout[0];
}

// ---------------- launch ----------------
extern "C" void kernel_launch(void* const* d_in, const int* in_sizes, int n_in,
                              void* d_out, int out_size) {
    const float* x    = (const float*)d_in[0];
    const void*  ei   = d_in[1];
    const float* W1   = (const float*)d_in[2];
    const float* b1   = (const float*)d_in[3];
    const float* W2   = (const float*)d_in[4];
    const float* b2   = (const float*)d_in[5];
    const float* Wout = (const float*)d_in[6];
    const float* bout = (const float*)d_in[7];
    float* out = (float*)d_out;

    __half *x16, *agg, *h16, *w1t, *w2t;
    cudaGetSymbolAddress((void**)&x16, g_x16);
    cudaGetSymbolAddress((void**)&agg, g_agg);
    cudaGetSymbolAddress((void**)&h16, g_h16);
    cudaGetSymbolAddress((void**)&w1t, g_W1t);
    cudaGetSymbolAddress((void**)&w2t, g_W2t);

    // graph build + weight prep; then dinv + prescaled x->fp16
    k_init<<<NN / 256, 256>>>((const int*)ei);                           // launch 1
    k_fillprep<<<(FP_W2 + 255) / 256, 256>>>(ei, W1, W2, w1t, w2t);      // launch 2
    k_prep2<<<(P2_F2H + 255) / 256, 256>>>(x, x16);                      // launch 3

    // layer 1: aggregate prescaled y0, GEMM (epilogue prescales h1 by dinv)
    k_agg_w<F1><<<NN * 32 / 256, 256>>>(x16, agg);                       // launch 4
    {
        dim3 grid(F2 / 128, NN / 128);
        k_gemm_h<F1><<<grid, 256>>>(agg, w1t, b1, h16);                  // launch 5
    }
    // layer 2: aggregate prescaled y1, GEMM fused with output head
    k_agg_w<F2><<<NN * 32 / 256, 256>>>(h16, agg);                       // launch 6
    {
        dim3 grid(F2 / 128, NN / 128);
        k_gemm_fin<F2><<<grid, 256>>>(agg, w2t, b2, Wout);               // launch 7
    }
    // finisher
    k_fin<<<NG / 256, 256>>>(bout, out);                                 // launch 8
}

// round 15
// speedup vs baseline: 1.1700x; 1.0015x over previous
#include <cuda_runtime.h>
#include <cuda_fp16.h>
#include <cstdint>

// Problem constants (fixed by the dataset)
#define NN 131072          // nodes
#define EE 4194304         // edges
#define F1 128             // input feature dim
#define F2 256             // hidden dim
#define SUB 16             // subgraph group size
#define NG (NN / SUB)      // 8192 output rows
#define CAPLOG 7           // 128 slots per node (max Poisson(32) degree << 128)
#define CAP (1 << CAPLOG)

// ---------------- device scratch (static, no allocation) ----------------
__device__ float  g_dinv[NN];
__device__ int    g_cursor[NN];
__device__ int    g_csrc[(size_t)NN * CAP];  // padded-bucket CSR (64MB)
__device__ int    g_edge64;
__device__ __half g_x16[(size_t)NN * F1];    // y0 = x*dinv in fp16
__device__ __half g_agg[(size_t)NN * F2];    // agg output (fp16)
__device__ __half g_h16[(size_t)NN * F2];    // y1 = h1*dinv in fp16
__device__ __half g_W1t[(size_t)F2 * F1];    // W1^T fp16  [256 x 128]
__device__ __half g_W2t[(size_t)F2 * F2];    // W2^T fp16  [256 x 256]
__device__ float  g_part[(size_t)NG * 4];    // fused-head partials

__device__ __forceinline__ uint32_t smem_u32(const void* p) {
    return (uint32_t)__cvta_generic_to_shared(p);
}

__device__ __forceinline__ void cp16(uint32_t smem_dst, const void* gsrc) {
    asm volatile("cp.async.cg.shared.global [%0], [%1], 16;"
                 :: "r"(smem_dst), "l"(gsrc));
}
__device__ __forceinline__ void cp_commit() {
    asm volatile("cp.async.commit_group;");
}
template <int N>
__device__ __forceinline__ void cp_wait() {
    asm volatile("cp.async.wait_group %0;" :: "n"(N));
}

// mma.sync m16n8k16 f16 (fp32 accumulate); generic PTX, sm_80+.
__device__ __forceinline__ void mma_f16(float* c, const uint32_t* a, const uint32_t* b) {
    asm volatile(
        "mma.sync.aligned.m16n8k16.row.col.f32.f16.f16.f32 "
        "{%0,%1,%2,%3}, {%4,%5,%6,%7}, {%8,%9}, {%0,%1,%2,%3};"
        : "+f"(c[0]), "+f"(c[1]), "+f"(c[2]), "+f"(c[3])
        : "r"(a[0]), "r"(a[1]), "r"(a[2]), "r"(a[3]),
          "r"(b[0]), "r"(b[1]));
}

// vectorized row-slice load/store of V half2 (V = 2 or 4)
template <int V> struct RowV { __half2 v[V]; };
template <int V>
__device__ __forceinline__ RowV<V> ldrow(const __half2* __restrict__ p) {
    RowV<V> r;
    if (V == 2) {
        uint2 u = *(const uint2*)p;
        r.v[0] = *(__half2*)&u.x; r.v[1] = *(__half2*)&u.y;
    } else {
        uint4 u = *(const uint4*)p;
        r.v[0] = *(__half2*)&u.x; r.v[1] = *(__half2*)&u.y;
        r.v[2] = *(__half2*)&u.z; r.v[3] = *(__half2*)&u.w;
    }
    return r;
}
template <int V>
__device__ __forceinline__ void strow(__half2* p, const RowV<V>& r) {
    if (V == 2) {
        uint2 u;
        u.x = *(const uint32_t*)&r.v[0]; u.y = *(const uint32_t*)&r.v[1];
        *(uint2*)p = u;
    } else {
        uint4 u;
        u.x = *(const uint32_t*)&r.v[0]; u.y = *(const uint32_t*)&r.v[1];
        u.z = *(const uint32_t*)&r.v[2]; u.w = *(const uint32_t*)&r.v[3];
        *(uint4*)p = u;
    }
}

// ---------------- init cursors + dtype detect ----------------
// int64 node indices < 2^31 => every odd 32-bit word of the array is 0.
__global__ void k_init(const int* __restrict__ ei32) {
    int i = blockIdx.x * blockDim.x + threadIdx.x;
    if (i < NN) g_cursor[i] = i << CAPLOG;
    if (blockIdx.x == 0) {
        int found = 0;
        for (int j = threadIdx.x; j < 2048; j += 256)
            if (ei32[2 * j + 1] != 0) found = 1;
        found = __syncthreads_or(found);
        if (threadIdx.x == 0) g_edge64 = found ? 0 : 1;
    }
}

// ---------------- merged fill + weight transpose ----------------
#define FP_FILL  (EE / 2)
#define FP_W1    (FP_FILL + F1 * 256)
#define FP_W2    (FP_W1 + F2 * 256)
__global__ void k_fillprep(const void* __restrict__ ei,
                           const float* __restrict__ W1,
                           const float* __restrict__ W2,
                           __half* __restrict__ w1t,
                           __half* __restrict__ w2t) {
    int idx = blockIdx.x * blockDim.x + threadIdx.x;
    if (idx < FP_FILL) {
        int e2 = idx;
        int s0, s1, d0, d1;
        if (g_edge64) {
            ulonglong2 s = ((const ulonglong2*)ei)[e2];
            ulonglong2 d = ((const ulonglong2*)ei)[EE / 2 + e2];
            s0 = (int)s.x; s1 = (int)s.y; d0 = (int)d.x; d1 = (int)d.y;
        } else {
            int2 s = ((const int2*)ei)[e2];
            int2 d = ((const int2*)ei)[EE / 2 + e2];
            s0 = s.x; s1 = s.y; d0 = d.x; d1 = d.y;
        }
        int p0 = atomicAdd(&g_cursor[d0], 1);
        if (p0 < ((d0 + 1) << CAPLOG)) g_csrc[p0] = s0;   // overflow guard
        int p1 = atomicAdd(&g_cursor[d1], 1);
        if (p1 < ((d1 + 1) << CAPLOG)) g_csrc[p1] = s1;
    } else if (idx < FP_W1) {
        int j = idx - FP_FILL;
        int k = j / 256, n = j % 256;
        w1t[(size_t)n * F1 + k] = __float2half_rn(W1[j]);
    } else if (idx < FP_W2) {
        int j = idx - FP_W1;
        int k = j / 256, n = j % 256;
        w2t[(size_t)n * F2 + k] = __float2half_rn(W2[j]);
    }
}

// ---------------- prep2: dinv + prescaled x->fp16 ----------------
#define P2_DINV NN
#define P2_F2H  (P2_DINV + NN * F1 / 4)
__global__ void k_prep2(const float* __restrict__ x, __half* __restrict__ x16) {
    int idx = blockIdx.x * blockDim.x + threadIdx.x;
    if (idx < P2_DINV) {
        int deg = g_cursor[idx] - (idx << CAPLOG) + 1;
        g_dinv[idx] = rsqrtf((float)deg);
    } else if (idx < P2_F2H) {
        int j = idx - P2_DINV;                 // over NN*F1/4
        int row = j >> 5;                      // j / (F1/4)
        int deg = g_cursor[row] - (row << CAPLOG) + 1;
        float di = rsqrtf((float)deg);
        float4 v = ((const float4*)x)[j];
        ((__half2*)x16)[2 * j    ] = __floats2half2_rn(v.x * di, v.y * di);
        ((__half2*)x16)[2 * j + 1] = __floats2half2_rn(v.z * di, v.w * di);
    }
}

// ---------------- warp-per-node aggregation (prescaled inputs) ----------
// Input rows y[s] = dinv[s]*h[s]; out[i,:] = fp16( dinv[i] * (y[i] + sum y[src]) )
// Round-14 skeleton + (a) int4 index load (16B-aligned: e0 = i<<7, step 4),
// (b) depth-1 pairwise HADD2 pre-reduction, flushed to fp32 per block.
template <int F>
__global__ void __launch_bounds__(256)
k_agg_w(const __half* __restrict__ h, __half* __restrict__ outp) {
    const int T = F / 2;          // half2 per row
    const int V = T / 32;         // half2 per lane: 2 (F1) or 4 (F2)
    int i = (blockIdx.x * 256 + threadIdx.x) >> 5;     // node id
    int lane = threadIdx.x & 31;
    const __half2* __restrict__ base = (const __half2*)h;
    float di = g_dinv[i];

    float acc[2 * V];
    {
        RowV<V> r = ldrow<V>(base + (size_t)i * T + lane * V);
#pragma unroll
        for (int v = 0; v < V; v++) {
            float2 f = __half22float2(r.v[v]);
            acc[2 * v    ] = f.x;
            acc[2 * v + 1] = f.y;
        }
    }

    int e0 = i << CAPLOG;
    int e1 = g_cursor[i];
    int e = e0;
    for (; e + 4 <= e1; e += 4) {
        int4 s4 = *(const int4*)&g_csrc[e];            // 16B-aligned
        RowV<V> r0 = ldrow<V>(base + (size_t)s4.x * T + lane * V);
        RowV<V> r1 = ldrow<V>(base + (size_t)s4.y * T + lane * V);
        RowV<V> r2 = ldrow<V>(base + (size_t)s4.z * T + lane * V);
        RowV<V> r3 = ldrow<V>(base + (size_t)s4.w * T + lane * V);
#pragma unroll
        for (int v = 0; v < V; v++) {
            __half2 h01 = __hadd2(r0.v[v], r1.v[v]);   // depth-1 fp16 tree
            __half2 h23 = __hadd2(r2.v[v], r3.v[v]);
            float2 f01 = __half22float2(h01);
            float2 f23 = __half22float2(h23);
            acc[2 * v    ] += f01.x; acc[2 * v + 1] += f01.y;
            acc[2 * v    ] += f23.x; acc[2 * v + 1] += f23.y;
        }
    }
    for (; e < e1; e++) {
        int s = g_csrc[e];
        RowV<V> r = ldrow<V>(base + (size_t)s * T + lane * V);
#pragma unroll
        for (int v = 0; v < V; v++) {
            float2 f = __half22float2(r.v[v]);
            acc[2 * v    ] += f.x;
            acc[2 * v + 1] += f.y;
        }
    }

    RowV<V> o;
#pragma unroll
    for (int v = 0; v < V; v++)
        o.v[v] = __floats2half2_rn(acc[2 * v] * di, acc[2 * v + 1] * di);
    strow<V>((__half2*)outp + (size_t)i * T + lane * V, o);
}

// ---------------- fp16 mma.sync GEMM, cp.async double-buffered ----------------
// out[M,256] = fp16( relu(A[M,K] @ Wt^T + bias) * dinv[row] )  (prescale for next agg)
template <int K>
__global__ void __launch_bounds__(256)
k_gemm_h(const __half* __restrict__ A, const __half* __restrict__ Wt,
         const float* __restrict__ bias, __half* __restrict__ out) {
    const int BK = 32, LD = BK + 8;
    __shared__ __half As[2][128][LD];
    __shared__ __half Bs[2][128][LD];

    int tid = threadIdx.x;
    int lane = tid & 31;
    int warp = tid >> 5;
    int warp_m = warp & 3;
    int warp_n = warp >> 2;
    int gid = lane >> 2;
    int tig = lane & 3;
    int m0 = blockIdx.y * 128;
    int n0 = blockIdx.x * 128;

    float c[2][8][4];
#pragma unroll
    for (int mm = 0; mm < 2; mm++)
#pragma unroll
        for (int nn = 0; nn < 8; nn++)
#pragma unroll
            for (int q = 0; q < 4; q++) c[mm][nn][q] = 0.0f;

    int srow0 = tid >> 2, sc0 = (tid & 3) * 8;
    int srow1 = (tid + 256) >> 2, sc1 = sc0;
    const int NCH = K / BK;

    cp16(smem_u32(&As[0][srow0][sc0]), &A[(size_t)(m0 + srow0) * K + sc0]);
    cp16(smem_u32(&Bs[0][srow0][sc0]), &Wt[(size_t)(n0 + srow0) * K + sc0]);
    cp16(smem_u32(&As[0][srow1][sc1]), &A[(size_t)(m0 + srow1) * K + sc1]);
    cp16(smem_u32(&Bs[0][srow1][sc1]), &Wt[(size_t)(n0 + srow1) * K + sc1]);
    cp_commit();

#pragma unroll
    for (int ch = 0; ch < NCH; ch++) {
        int buf = ch & 1;
        if (ch + 1 < NCH) {
            int nb = buf ^ 1, kofs = (ch + 1) * BK;
            cp16(smem_u32(&As[nb][srow0][sc0]), &A[(size_t)(m0 + srow0) * K + kofs + sc0]);
            cp16(smem_u32(&Bs[nb][srow0][sc0]), &Wt[(size_t)(n0 + srow0) * K + kofs + sc0]);
            cp16(smem_u32(&As[nb][srow1][sc1]), &A[(size_t)(m0 + srow1) * K + kofs + sc1]);
            cp16(smem_u32(&Bs[nb][srow1][sc1]), &Wt[(size_t)(n0 + srow1) * K + kofs + sc1]);
        }
        cp_commit();
        cp_wait<1>();
        __syncthreads();

#pragma unroll
        for (int kk = 0; kk < 2; kk++) {
            int kb = kk * 16;
            uint32_t a[2][4], b[8][2];
#pragma unroll
            for (int mm = 0; mm < 2; mm++) {
                int r = warp_m * 32 + mm * 16;
                a[mm][0] = *(const uint32_t*)&As[buf][r + gid    ][kb + 2 * tig    ];
                a[mm][1] = *(const uint32_t*)&As[buf][r + gid + 8][kb + 2 * tig    ];
                a[mm][2] = *(const uint32_t*)&As[buf][r + gid    ][kb + 2 * tig + 8];
                a[mm][3] = *(const uint32_t*)&As[buf][r + gid + 8][kb + 2 * tig + 8];
            }
#pragma unroll
            for (int nn = 0; nn < 8; nn++) {
                int r = warp_n * 64 + nn * 8;
                b[nn][0] = *(const uint32_t*)&Bs[buf][r + gid][kb + 2 * tig    ];
                b[nn][1] = *(const uint32_t*)&Bs[buf][r + gid][kb + 2 * tig + 8];
            }
#pragma unroll
            for (int mm = 0; mm < 2; mm++)
#pragma unroll
                for (int nn = 0; nn < 8; nn++)
                    mma_f16(c[mm][nn], a[mm], b[nn]);
        }
        __syncthreads();
    }

#pragma unroll
    for (int mm = 0; mm < 2; mm++) {
        int rbase = m0 + warp_m * 32 + mm * 16;
        float dA = g_dinv[rbase + gid];
        float dB = g_dinv[rbase + gid + 8];
#pragma unroll
        for (int nn = 0; nn < 8; nn++) {
            int col = n0 + warp_n * 64 + nn * 8 + tig * 2;
            float bi0 = bias[col], bi1 = bias[col + 1];
            float v00 = fmaxf(c[mm][nn][0] + bi0, 0.0f) * dA;
            float v01 = fmaxf(c[mm][nn][1] + bi1, 0.0f) * dA;
            float v10 = fmaxf(c[mm][nn][2] + bi0, 0.0f) * dB;
            float v11 = fmaxf(c[mm][nn][3] + bi1, 0.0f) * dB;
            *(__half2*)&out[(size_t)(rbase + gid    ) * F2 + col] = __floats2half2_rn(v00, v01);
            *(__half2*)&out[(size_t)(rbase + gid + 8) * F2 + col] = __floats2half2_rn(v10, v11);
        }
    }
}

// ---------------- layer-2 GEMM with fused output head (no prescale) --------
template <int K>
__global__ void __launch_bounds__(256)
k_gemm_fin(const __half* __restrict__ A, const __half* __restrict__ Wt,
           const float* __restrict__ bias, const float* __restrict__ Wout) {
    const int BK = 32, LD = BK + 8;
    __shared__ __half As[2][128][LD];
    __shared__ __half Bs[2][128][LD];

    int tid = threadIdx.x;
    int lane = tid & 31;
    int warp = tid >> 5;
    int warp_m = warp & 3;
    int warp_n = warp >> 2;
    int gid = lane >> 2;
    int tig = lane & 3;
    int m0 = blockIdx.y * 128;
    int n0 = blockIdx.x * 128;

    float c[2][8][4];
#pragma unroll
    for (int mm = 0; mm < 2; mm++)
#pragma unroll
        for (int nn = 0; nn < 8; nn++)
#pragma unroll
            for (int q = 0; q < 4; q++) c[mm][nn][q] = 0.0f;

    int srow0 = tid >> 2, sc0 = (tid & 3) * 8;
    int srow1 = (tid + 256) >> 2, sc1 = sc0;
    const int NCH = K / BK;

    cp16(smem_u32(&As[0][srow0][sc0]), &A[(size_t)(m0 + srow0) * K + sc0]);
    cp16(smem_u32(&Bs[0][srow0][sc0]), &Wt[(size_t)(n0 + srow0) * K + sc0]);
    cp16(smem_u32(&As[0][srow1][sc1]), &A[(size_t)(m0 + srow1) * K + sc1]);
    cp16(smem_u32(&Bs[0][srow1][sc1]), &Wt[(size_t)(n0 + srow1) * K + sc1]);
    cp_commit();

#pragma unroll
    for (int ch = 0; ch < NCH; ch++) {
        int buf = ch & 1;
        if (ch + 1 < NCH) {
            int nb = buf ^ 1, kofs = (ch + 1) * BK;
            cp16(smem_u32(&As[nb][srow0][sc0]), &A[(size_t)(m0 + srow0) * K + kofs + sc0]);
            cp16(smem_u32(&Bs[nb][srow0][sc0]), &Wt[(size_t)(n0 + srow0) * K + kofs + sc0]);
            cp16(smem_u32(&As[nb][srow1][sc1]), &A[(size_t)(m0 + srow1) * K + kofs + sc1]);
            cp16(smem_u32(&Bs[nb][srow1][sc1]), &Wt[(size_t)(n0 + srow1) * K + kofs + sc1]);
        }
        cp_commit();
        cp_wait<1>();
        __syncthreads();

#pragma unroll
        for (int kk = 0; kk < 2; kk++) {
            int kb = kk * 16;
            uint32_t a[2][4], b[8][2];
#pragma unroll
            for (int mm = 0; mm < 2; mm++) {
                int r = warp_m * 32 + mm * 16;
                a[mm][0] = *(const uint32_t*)&As[buf][r + gid    ][kb + 2 * tig    ];
                a[mm][1] = *(const uint32_t*)&As[buf][r + gid + 8][kb + 2 * tig    ];
                a[mm][2] = *(const uint32_t*)&As[buf][r + gid    ][kb + 2 * tig + 8];
                a[mm][3] = *(const uint32_t*)&As[buf][r + gid + 8][kb + 2 * tig + 8];
            }
#pragma unroll
            for (int nn = 0; nn < 8; nn++) {
                int r = warp_n * 64 + nn * 8;
                b[nn][0] = *(const uint32_t*)&Bs[buf][r + gid][kb + 2 * tig    ];
                b[nn][1] = *(const uint32_t*)&Bs[buf][r + gid][kb + 2 * tig + 8];
            }
#pragma unroll
            for (int mm = 0; mm < 2; mm++)
#pragma unroll
                for (int nn = 0; nn < 8; nn++)
                    mma_f16(c[mm][nn], a[mm], b[nn]);
        }
        __syncthreads();
    }

    // fused epilogue: relu(c + bias) dot Wout[(row&15)*256 + col]
    float vsum[2] = {0.0f, 0.0f};
#pragma unroll
    for (int mm = 0; mm < 2; mm++) {
#pragma unroll
        for (int nn = 0; nn < 8; nn++) {
            int col = n0 + warp_n * 64 + nn * 8 + tig * 2;
            float bi0 = bias[col], bi1 = bias[col + 1];
            float v00 = fmaxf(c[mm][nn][0] + bi0, 0.0f);
            float v01 = fmaxf(c[mm][nn][1] + bi1, 0.0f);
            float v10 = fmaxf(c[mm][nn][2] + bi0, 0.0f);
            float v11 = fmaxf(c[mm][nn][3] + bi1, 0.0f);
            float w00 = Wout[gid * 256 + col];
            float w01 = Wout[gid * 256 + col + 1];
            float w10 = Wout[(gid + 8) * 256 + col];
            float w11 = Wout[(gid + 8) * 256 + col + 1];
            vsum[mm] += v00 * w00 + v01 * w01 + v10 * w10 + v11 * w11;
        }
    }
#pragma unroll
    for (int off = 16; off > 0; off >>= 1) {
        vsum[0] += __shfl_down_sync(0xFFFFFFFF, vsum[0], off);
        vsum[1] += __shfl_down_sync(0xFFFFFFFF, vsum[1], off);
    }
    if (lane == 0) {
        int quarter = blockIdx.x * 2 + warp_n;
#pragma unroll
        for (int mm = 0; mm < 2; mm++) {
            int group = (m0 >> 4) + warp_m * 2 + mm;
            g_part[(size_t)group * 4 + quarter] = vsum[mm];
        }
    }
}

// ---------------- finisher: sum 4 partials + bias ----------------
__global__ void k_fin(const float* __restrict__ bout, float* __restrict__ out) {
    int g = blockIdx.x * blockDim.x + threadIdx.x;
    if (g >= NG) return;
    float4 p = *(const float4*)&g_part[(size_t)g * 4];
    out[g] = p.x + p.y + p.z + p.w + bout[0];
}

// ---------------- launch ----------------
extern "C" void kernel_launch(void* const* d_in, const int* in_sizes, int n_in,
                              void* d_out, int out_size) {
    const float* x    = (const float*)d_in[0];
    const void*  ei   = d_in[1];
    const float* W1   = (const float*)d_in[2];
    const float* b1   = (const float*)d_in[3];
    const float* W2   = (const float*)d_in[4];
    const float* b2   = (const float*)d_in[5];
    const float* Wout = (const float*)d_in[6];
    const float* bout = (const float*)d_in[7];
    float* out = (float*)d_out;

    __half *x16, *agg, *h16, *w1t, *w2t;
    cudaGetSymbolAddress((void**)&x16, g_x16);
    cudaGetSymbolAddress((void**)&agg, g_agg);
    cudaGetSymbolAddress((void**)&h16, g_h16);
    cudaGetSymbolAddress((void**)&w1t, g_W1t);
    cudaGetSymbolAddress((void**)&w2t, g_W2t);

    // graph build + weight prep; then dinv + prescaled x->fp16
    k_init<<<NN / 256, 256>>>((const int*)ei);                           // launch 1
    k_fillprep<<<(FP_W2 + 255) / 256, 256>>>(ei, W1, W2, w1t, w2t);      // launch 2
    k_prep2<<<(P2_F2H + 255) / 256, 256>>>(x, x16);                      // launch 3

    // layer 1: aggregate prescaled y0, GEMM (epilogue prescales h1 by dinv)
    k_agg_w<F1><<<NN * 32 / 256, 256>>>(x16, agg);                       // launch 4
    {
        dim3 grid(F2 / 128, NN / 128);
        k_gemm_h<F1><<<grid, 256>>>(agg, w1t, b1, h16);                  // launch 5
    }
    // layer 2: aggregate prescaled y1, GEMM fused with output head
    k_agg_w<F2><<<NN * 32 / 256, 256>>>(h16, agg);                       // launch 6
    {
        dim3 grid(F2 / 128, NN / 128);
        k_gemm_fin<F2><<<grid, 256>>>(agg, w2t, b2, Wout);               // launch 7
    }
    // finisher
    k_fin<<<NG / 256, 256>>>(bout, out);                                 // launch 8
}

// round 16
// speedup vs baseline: 1.2141x; 1.0377x over previous
#include <cuda_runtime.h>
#include <cuda_fp16.h>
#include <cstdint>

// Problem constants (fixed by the dataset)
#define NN 131072          // nodes
#define EE 4194304         // edges
#define F1 128             // input feature dim
#define F2 256             // hidden dim
#define SUB 16             // subgraph group size
#define NG (NN / SUB)      // 8192 output rows
#define CAPLOG 7           // 128 slots per node (max Poisson(32) degree << 128)
#define CAP (1 << CAPLOG)

// ---------------- device scratch (static, no allocation) ----------------
__device__ float  g_dinv[NN];
__device__ int    g_cursor[NN];
__device__ int    g_csrc[(size_t)NN * CAP];  // padded-bucket CSR (64MB)
__device__ int    g_edge64;
__device__ __half g_x16[(size_t)NN * F1];    // y0 = x*dinv in fp16
__device__ __half g_agg[(size_t)NN * F2];    // agg output (fp16)
__device__ __half g_h16[(size_t)NN * F2];    // y1 = h1*dinv in fp16
__device__ __half g_W1t[(size_t)F2 * F1];    // W1^T fp16  [256 x 128]
__device__ __half g_W2t[(size_t)F2 * F2];    // W2^T fp16  [256 x 256]
__device__ float  g_part[(size_t)NG * 4];    // fused-head partials

__device__ __forceinline__ uint32_t smem_u32(const void* p) {
    return (uint32_t)__cvta_generic_to_shared(p);
}

__device__ __forceinline__ void cp16(uint32_t smem_dst, const void* gsrc) {
    asm volatile("cp.async.cg.shared.global [%0], [%1], 16;"
                 :: "r"(smem_dst), "l"(gsrc));
}
__device__ __forceinline__ void cp_commit() {
    asm volatile("cp.async.commit_group;");
}
template <int N>
__device__ __forceinline__ void cp_wait() {
    asm volatile("cp.async.wait_group %0;" :: "n"(N));
}

// mma.sync m16n8k16 f16 (fp32 accumulate); generic PTX, sm_80+.
__device__ __forceinline__ void mma_f16(float* c, const uint32_t* a, const uint32_t* b) {
    asm volatile(
        "mma.sync.aligned.m16n8k16.row.col.f32.f16.f16.f32 "
        "{%0,%1,%2,%3}, {%4,%5,%6,%7}, {%8,%9}, {%0,%1,%2,%3};"
        : "+f"(c[0]), "+f"(c[1]), "+f"(c[2]), "+f"(c[3])
        : "r"(a[0]), "r"(a[1]), "r"(a[2]), "r"(a[3]),
          "r"(b[0]), "r"(b[1]));
}

// vectorized row-slice load/store of V half2 (V = 2 or 4)
template <int V> struct RowV { __half2 v[V]; };
template <int V>
__device__ __forceinline__ RowV<V> ldrow(const __half2* __restrict__ p) {
    RowV<V> r;
    if (V == 2) {
        uint2 u = *(const uint2*)p;
        r.v[0] = *(__half2*)&u.x; r.v[1] = *(__half2*)&u.y;
    } else {
        uint4 u = *(const uint4*)p;
        r.v[0] = *(__half2*)&u.x; r.v[1] = *(__half2*)&u.y;
        r.v[2] = *(__half2*)&u.z; r.v[3] = *(__half2*)&u.w;
    }
    return r;
}
template <int V>
__device__ __forceinline__ void strow(__half2* p, const RowV<V>& r) {
    if (V == 2) {
        uint2 u;
        u.x = *(const uint32_t*)&r.v[0]; u.y = *(const uint32_t*)&r.v[1];
        *(uint2*)p = u;
    } else {
        uint4 u;
        u.x = *(const uint32_t*)&r.v[0]; u.y = *(const uint32_t*)&r.v[1];
        u.z = *(const uint32_t*)&r.v[2]; u.w = *(const uint32_t*)&r.v[3];
        *(uint4*)p = u;
    }
}

// ---------------- init cursors + dtype detect ----------------
// int64 node indices < 2^31 => every odd 32-bit word of the array is 0.
__global__ void k_init(const int* __restrict__ ei32) {
    int i = blockIdx.x * blockDim.x + threadIdx.x;
    if (i < NN) g_cursor[i] = i << CAPLOG;
    if (blockIdx.x == 0) {
        int found = 0;
        for (int j = threadIdx.x; j < 2048; j += 256)
            if (ei32[2 * j + 1] != 0) found = 1;
        found = __syncthreads_or(found);
        if (threadIdx.x == 0) g_edge64 = found ? 0 : 1;
    }
}

// ---------------- merged fill + weight transpose ----------------
#define FP_FILL  (EE / 2)
#define FP_W1    (FP_FILL + F1 * 256)
#define FP_W2    (FP_W1 + F2 * 256)
__global__ void k_fillprep(const void* __restrict__ ei,
                           const float* __restrict__ W1,
                           const float* __restrict__ W2,
                           __half* __restrict__ w1t,
                           __half* __restrict__ w2t) {
    int idx = blockIdx.x * blockDim.x + threadIdx.x;
    if (idx < FP_FILL) {
        int e2 = idx;
        int s0, s1, d0, d1;
        if (g_edge64) {
            ulonglong2 s = ((const ulonglong2*)ei)[e2];
            ulonglong2 d = ((const ulonglong2*)ei)[EE / 2 + e2];
            s0 = (int)s.x; s1 = (int)s.y; d0 = (int)d.x; d1 = (int)d.y;
        } else {
            int2 s = ((const int2*)ei)[e2];
            int2 d = ((const int2*)ei)[EE / 2 + e2];
            s0 = s.x; s1 = s.y; d0 = d.x; d1 = d.y;
        }
        int p0 = atomicAdd(&g_cursor[d0], 1);
        if (p0 < ((d0 + 1) << CAPLOG)) g_csrc[p0] = s0;   // overflow guard
        int p1 = atomicAdd(&g_cursor[d1], 1);
        if (p1 < ((d1 + 1) << CAPLOG)) g_csrc[p1] = s1;
    } else if (idx < FP_W1) {
        int j = idx - FP_FILL;
        int k = j / 256, n = j % 256;
        w1t[(size_t)n * F1 + k] = __float2half_rn(W1[j]);
    } else if (idx < FP_W2) {
        int j = idx - FP_W1;
        int k = j / 256, n = j % 256;
        w2t[(size_t)n * F2 + k] = __float2half_rn(W2[j]);
    }
}

// ---------------- prep2: dinv + prescaled x->fp16 ----------------
#define P2_DINV NN
#define P2_F2H  (P2_DINV + NN * F1 / 4)
__global__ void k_prep2(const float* __restrict__ x, __half* __restrict__ x16) {
    int idx = blockIdx.x * blockDim.x + threadIdx.x;
    if (idx < P2_DINV) {
        int deg = g_cursor[idx] - (idx << CAPLOG) + 1;
        g_dinv[idx] = rsqrtf((float)deg);
    } else if (idx < P2_F2H) {
        int j = idx - P2_DINV;                 // over NN*F1/4
        int row = j >> 5;                      // j / (F1/4)
        int deg = g_cursor[row] - (row << CAPLOG) + 1;
        float di = rsqrtf((float)deg);
        float4 v = ((const float4*)x)[j];
        ((__half2*)x16)[2 * j    ] = __floats2half2_rn(v.x * di, v.y * di);
        ((__half2*)x16)[2 * j + 1] = __floats2half2_rn(v.z * di, v.w * di);
    }
}

// ---------------- warp-per-node aggregation (prescaled inputs) ----------
// Input rows y[s] = dinv[s]*h[s]; out[i,:] = fp16( dinv[i] * (y[i] + sum y[src]) )
// Round-15 skeleton; full depth-2 fp16 reduction tree per 4-edge block
// (3x HADD2 + 1 cvt-pair + 2 FADD vs previous 2x HADD2 + 2 cvt-pair + 4 FADD).
template <int F>
__global__ void __launch_bounds__(256)
k_agg_w(const __half* __restrict__ h, __half* __restrict__ outp) {
    const int T = F / 2;          // half2 per row
    const int V = T / 32;         // half2 per lane: 2 (F1) or 4 (F2)
    int i = (blockIdx.x * 256 + threadIdx.x) >> 5;     // node id
    int lane = threadIdx.x & 31;
    const __half2* __restrict__ base = (const __half2*)h;
    float di = g_dinv[i];

    float acc[2 * V];
    {
        RowV<V> r = ldrow<V>(base + (size_t)i * T + lane * V);
#pragma unroll
        for (int v = 0; v < V; v++) {
            float2 f = __half22float2(r.v[v]);
            acc[2 * v    ] = f.x;
            acc[2 * v + 1] = f.y;
        }
    }

    int e0 = i << CAPLOG;
    int e1 = g_cursor[i];
    int e = e0;
    for (; e + 4 <= e1; e += 4) {
        int4 s4 = *(const int4*)&g_csrc[e];            // 16B-aligned
        RowV<V> r0 = ldrow<V>(base + (size_t)s4.x * T + lane * V);
        RowV<V> r1 = ldrow<V>(base + (size_t)s4.y * T + lane * V);
        RowV<V> r2 = ldrow<V>(base + (size_t)s4.z * T + lane * V);
        RowV<V> r3 = ldrow<V>(base + (size_t)s4.w * T + lane * V);
#pragma unroll
        for (int v = 0; v < V; v++) {
            __half2 h01 = __hadd2(r0.v[v], r1.v[v]);   // depth-2 fp16 tree
            __half2 h23 = __hadd2(r2.v[v], r3.v[v]);
            __half2 hs  = __hadd2(h01, h23);
            float2 f = __half22float2(hs);
            acc[2 * v    ] += f.x;
            acc[2 * v + 1] += f.y;
        }
    }
    for (; e < e1; e++) {
        int s = g_csrc[e];
        RowV<V> r = ldrow<V>(base + (size_t)s * T + lane * V);
#pragma unroll
        for (int v = 0; v < V; v++) {
            float2 f = __half22float2(r.v[v]);
            acc[2 * v    ] += f.x;
            acc[2 * v + 1] += f.y;
        }
    }

    RowV<V> o;
#pragma unroll
    for (int v = 0; v < V; v++)
        o.v[v] = __floats2half2_rn(acc[2 * v] * di, acc[2 * v + 1] * di);
    strow<V>((__half2*)outp + (size_t)i * T + lane * V, o);
}

// ---------------- fp16 mma.sync GEMM, cp.async double-buffered ----------------
// out[M,256] = fp16( relu(A[M,K] @ Wt^T + bias) * dinv[row] )  (prescale for next agg)
template <int K>
__global__ void __launch_bounds__(256)
k_gemm_h(const __half* __restrict__ A, const __half* __restrict__ Wt,
         const float* __restrict__ bias, __half* __restrict__ out) {
    const int BK = 32, LD = BK + 8;
    __shared__ __half As[2][128][LD];
    __shared__ __half Bs[2][128][LD];

    int tid = threadIdx.x;
    int lane = tid & 31;
    int warp = tid >> 5;
    int warp_m = warp & 3;
    int warp_n = warp >> 2;
    int gid = lane >> 2;
    int tig = lane & 3;
    int m0 = blockIdx.y * 128;
    int n0 = blockIdx.x * 128;

    float c[2][8][4];
#pragma unroll
    for (int mm = 0; mm < 2; mm++)
#pragma unroll
        for (int nn = 0; nn < 8; nn++)
#pragma unroll
            for (int q = 0; q < 4; q++) c[mm][nn][q] = 0.0f;

    int srow0 = tid >> 2, sc0 = (tid & 3) * 8;
    int srow1 = (tid + 256) >> 2, sc1 = sc0;
    const int NCH = K / BK;

    cp16(smem_u32(&As[0][srow0][sc0]), &A[(size_t)(m0 + srow0) * K + sc0]);
    cp16(smem_u32(&Bs[0][srow0][sc0]), &Wt[(size_t)(n0 + srow0) * K + sc0]);
    cp16(smem_u32(&As[0][srow1][sc1]), &A[(size_t)(m0 + srow1) * K + sc1]);
    cp16(smem_u32(&Bs[0][srow1][sc1]), &Wt[(size_t)(n0 + srow1) * K + sc1]);
    cp_commit();

#pragma unroll
    for (int ch = 0; ch < NCH; ch++) {
        int buf = ch & 1;
        if (ch + 1 < NCH) {
            int nb = buf ^ 1, kofs = (ch + 1) * BK;
            cp16(smem_u32(&As[nb][srow0][sc0]), &A[(size_t)(m0 + srow0) * K + kofs + sc0]);
            cp16(smem_u32(&Bs[nb][srow0][sc0]), &Wt[(size_t)(n0 + srow0) * K + kofs + sc0]);
            cp16(smem_u32(&As[nb][srow1][sc1]), &A[(size_t)(m0 + srow1) * K + kofs + sc1]);
            cp16(smem_u32(&Bs[nb][srow1][sc1]), &Wt[(size_t)(n0 + srow1) * K + kofs + sc1]);
        }
        cp_commit();
        cp_wait<1>();
        __syncthreads();

#pragma unroll
        for (int kk = 0; kk < 2; kk++) {
            int kb = kk * 16;
            uint32_t a[2][4], b[8][2];
#pragma unroll
            for (int mm = 0; mm < 2; mm++) {
                int r = warp_m * 32 + mm * 16;
                a[mm][0] = *(const uint32_t*)&As[buf][r + gid    ][kb + 2 * tig    ];
                a[mm][1] = *(const uint32_t*)&As[buf][r + gid + 8][kb + 2 * tig    ];
                a[mm][2] = *(const uint32_t*)&As[buf][r + gid    ][kb + 2 * tig + 8];
                a[mm][3] = *(const uint32_t*)&As[buf][r + gid + 8][kb + 2 * tig + 8];
            }
#pragma unroll
            for (int nn = 0; nn < 8; nn++) {
                int r = warp_n * 64 + nn * 8;
                b[nn][0] = *(const uint32_t*)&Bs[buf][r + gid][kb + 2 * tig    ];
                b[nn][1] = *(const uint32_t*)&Bs[buf][r + gid][kb + 2 * tig + 8];
            }
#pragma unroll
            for (int mm = 0; mm < 2; mm++)
#pragma unroll
                for (int nn = 0; nn < 8; nn++)
                    mma_f16(c[mm][nn], a[mm], b[nn]);
        }
        __syncthreads();
    }

#pragma unroll
    for (int mm = 0; mm < 2; mm++) {
        int rbase = m0 + warp_m * 32 + mm * 16;
        float dA = g_dinv[rbase + gid];
        float dB = g_dinv[rbase + gid + 8];
#pragma unroll
        for (int nn = 0; nn < 8; nn++) {
            int col = n0 + warp_n * 64 + nn * 8 + tig * 2;
            float bi0 = bias[col], bi1 = bias[col + 1];
            float v00 = fmaxf(c[mm][nn][0] + bi0, 0.0f) * dA;
            float v01 = fmaxf(c[mm][nn][1] + bi1, 0.0f) * dA;
            float v10 = fmaxf(c[mm][nn][2] + bi0, 0.0f) * dB;
            float v11 = fmaxf(c[mm][nn][3] + bi1, 0.0f) * dB;
            *(__half2*)&out[(size_t)(rbase + gid    ) * F2 + col] = __floats2half2_rn(v00, v01);
            *(__half2*)&out[(size_t)(rbase + gid + 8) * F2 + col] = __floats2half2_rn(v10, v11);
        }
    }
}

// ---------------- layer-2 GEMM with fused output head (no prescale) --------
template <int K>
__global__ void __launch_bounds__(256)
k_gemm_fin(const __half* __restrict__ A, const __half* __restrict__ Wt,
           const float* __restrict__ bias, const float* __restrict__ Wout) {
    const int BK = 32, LD = BK + 8;
    __shared__ __half As[2][128][LD];
    __shared__ __half Bs[2][128][LD];

    int tid = threadIdx.x;
    int lane = tid & 31;
    int warp = tid >> 5;
    int warp_m = warp & 3;
    int warp_n = warp >> 2;
    int gid = lane >> 2;
    int tig = lane & 3;
    int m0 = blockIdx.y * 128;
    int n0 = blockIdx.x * 128;

    float c[2][8][4];
#pragma unroll
    for (int mm = 0; mm < 2; mm++)
#pragma unroll
        for (int nn = 0; nn < 8; nn++)
#pragma unroll
            for (int q = 0; q < 4; q++) c[mm][nn][q] = 0.0f;

    int srow0 = tid >> 2, sc0 = (tid & 3) * 8;
    int srow1 = (tid + 256) >> 2, sc1 = sc0;
    const int NCH = K / BK;

    cp16(smem_u32(&As[0][srow0][sc0]), &A[(size_t)(m0 + srow0) * K + sc0]);
    cp16(smem_u32(&Bs[0][srow0][sc0]), &Wt[(size_t)(n0 + srow0) * K + sc0]);
    cp16(smem_u32(&As[0][srow1][sc1]), &A[(size_t)(m0 + srow1) * K + sc1]);
    cp16(smem_u32(&Bs[0][srow1][sc1]), &Wt[(size_t)(n0 + srow1) * K + sc1]);
    cp_commit();

#pragma unroll
    for (int ch = 0; ch < NCH; ch++) {
        int buf = ch & 1;
        if (ch + 1 < NCH) {
            int nb = buf ^ 1, kofs = (ch + 1) * BK;
            cp16(smem_u32(&As[nb][srow0][sc0]), &A[(size_t)(m0 + srow0) * K + kofs + sc0]);
            cp16(smem_u32(&Bs[nb][srow0][sc0]), &Wt[(size_t)(n0 + srow0) * K + kofs + sc0]);
            cp16(smem_u32(&As[nb][srow1][sc1]), &A[(size_t)(m0 + srow1) * K + kofs + sc1]);
            cp16(smem_u32(&Bs[nb][srow1][sc1]), &Wt[(size_t)(n0 + srow1) * K + kofs + sc1]);
        }
        cp_commit();
        cp_wait<1>();
        __syncthreads();

#pragma unroll
        for (int kk = 0; kk < 2; kk++) {
            int kb = kk * 16;
            uint32_t a[2][4], b[8][2];
#pragma unroll
            for (int mm = 0; mm < 2; mm++) {
                int r = warp_m * 32 + mm * 16;
                a[mm][0] = *(const uint32_t*)&As[buf][r + gid    ][kb + 2 * tig    ];
                a[mm][1] = *(const uint32_t*)&As[buf][r + gid + 8][kb + 2 * tig    ];
                a[mm][2] = *(const uint32_t*)&As[buf][r + gid    ][kb + 2 * tig + 8];
                a[mm][3] = *(const uint32_t*)&As[buf][r + gid + 8][kb + 2 * tig + 8];
            }
#pragma unroll
            for (int nn = 0; nn < 8; nn++) {
                int r = warp_n * 64 + nn * 8;
                b[nn][0] = *(const uint32_t*)&Bs[buf][r + gid][kb + 2 * tig    ];
                b[nn][1] = *(const uint32_t*)&Bs[buf][r + gid][kb + 2 * tig + 8];
            }
#pragma unroll
            for (int mm = 0; mm < 2; mm++)
#pragma unroll
                for (int nn = 0; nn < 8; nn++)
                    mma_f16(c[mm][nn], a[mm], b[nn]);
        }
        __syncthreads();
    }

    // fused epilogue: relu(c + bias) dot Wout[(row&15)*256 + col]
    float vsum[2] = {0.0f, 0.0f};
#pragma unroll
    for (int mm = 0; mm < 2; mm++) {
#pragma unroll
        for (int nn = 0; nn < 8; nn++) {
            int col = n0 + warp_n * 64 + nn * 8 + tig * 2;
            float bi0 = bias[col], bi1 = bias[col + 1];
            float v00 = fmaxf(c[mm][nn][0] + bi0, 0.0f);
            float v01 = fmaxf(c[mm][nn][1] + bi1, 0.0f);
            float v10 = fmaxf(c[mm][nn][2] + bi0, 0.0f);
            float v11 = fmaxf(c[mm][nn][3] + bi1, 0.0f);
            float w00 = Wout[gid * 256 + col];
            float w01 = Wout[gid * 256 + col + 1];
            float w10 = Wout[(gid + 8) * 256 + col];
            float w11 = Wout[(gid + 8) * 256 + col + 1];
            vsum[mm] += v00 * w00 + v01 * w01 + v10 * w10 + v11 * w11;
        }
    }
#pragma unroll
    for (int off = 16; off > 0; off >>= 1) {
        vsum[0] += __shfl_down_sync(0xFFFFFFFF, vsum[0], off);
        vsum[1] += __shfl_down_sync(0xFFFFFFFF, vsum[1], off);
    }
    if (lane == 0) {
        int quarter = blockIdx.x * 2 + warp_n;
#pragma unroll
        for (int mm = 0; mm < 2; mm++) {
            int group = (m0 >> 4) + warp_m * 2 + mm;
            g_part[(size_t)group * 4 + quarter] = vsum[mm];
        }
    }
}

// ---------------- finisher: sum 4 partials + bias ----------------
__global__ void k_fin(const float* __restrict__ bout, float* __restrict__ out) {
    int g = blockIdx.x * blockDim.x + threadIdx.x;
    if (g >= NG) return;
    float4 p = *(const float4*)&g_part[(size_t)g * 4];
    out[g] = p.x + p.y + p.z + p.w + bout[0];
}

// ---------------- launch ----------------
extern "C" void kernel_launch(void* const* d_in, const int* in_sizes, int n_in,
                              void* d_out, int out_size) {
    const float* x    = (const float*)d_in[0];
    const void*  ei   = d_in[1];
    const float* W1   = (const float*)d_in[2];
    const float* b1   = (const float*)d_in[3];
    const float* W2   = (const float*)d_in[4];
    const float* b2   = (const float*)d_in[5];
    const float* Wout = (const float*)d_in[6];
    const float* bout = (const float*)d_in[7];
    float* out = (float*)d_out;

    __half *x16, *agg, *h16, *w1t, *w2t;
    cudaGetSymbolAddress((void**)&x16, g_x16);
    cudaGetSymbolAddress((void**)&agg, g_agg);
    cudaGetSymbolAddress((void**)&h16, g_h16);
    cudaGetSymbolAddress((void**)&w1t, g_W1t);
    cudaGetSymbolAddress((void**)&w2t, g_W2t);

    // graph build + weight prep; then dinv + prescaled x->fp16
    k_init<<<NN / 256, 256>>>((const int*)ei);                           // launch 1
    k_fillprep<<<(FP_W2 + 255) / 256, 256>>>(ei, W1, W2, w1t, w2t);      // launch 2
    k_prep2<<<(P2_F2H + 255) / 256, 256>>>(x, x16);                      // launch 3

    // layer 1: aggregate prescaled y0, GEMM (epilogue prescales h1 by dinv)
    k_agg_w<F1><<<NN * 32 / 256, 256>>>(x16, agg);                       // launch 4
    {
        dim3 grid(F2 / 128, NN / 128);
        k_gemm_h<F1><<<grid, 256>>>(agg, w1t, b1, h16);                  // launch 5
    }
    // layer 2: aggregate prescaled y1, GEMM fused with output head
    k_agg_w<F2><<<NN * 32 / 256, 256>>>(h16, agg);                       // launch 6
    {
        dim3 grid(F2 / 128, NN / 128);
        k_gemm_fin<F2><<<grid, 256>>>(agg, w2t, b2, Wout);               // launch 7
    }
    // finisher
    k_fin<<<NG / 256, 256>>>(bout, out);                                 // launch 8
}